// round 6
// baseline (speedup 1.0000x reference)
#include <cuda_runtime.h>
#include <cuda_fp16.h>
#include <cstdint>

// Problem constants
#define N_SENT 65536
#define D_DIM  2304
#define N_BAGS 4096
#define C_CLS  53
#define N_PAD  64
#define NJ     7           // n8 blocks computed (cols 0..55); 56..63 are zero pad
#define BM     128
#define KC     64
#define NCHUNK (D_DIM / KC)   // 36
#define NTHR   256

typedef unsigned long long ull;

// ---------------- global scratch ----------------
__device__ __half g_BtH[N_PAD * D_DIM];   // W^T [n][k] f16 hi (zero-padded rows)
__device__ __half g_BtL[N_PAD * D_DIM];   // f16 lo residual
__device__ float  g_probs[(size_t)N_SENT * C_CLS];
__device__ ull    g_best[N_BAGS];

// ---------------- smem geometry (halves) ----------------
#define A_STRIDE 72
#define B_STRIDE 72
#define A_STAGE  (BM * A_STRIDE)      // 9216
#define B_STAGE  (N_PAD * B_STRIDE)   // 4608
#define SMEM_BYTES ((4 * A_STAGE + 4 * B_STAGE) * 2)   // 110592
#define L_STRIDE 65

// ---------------- PTX helpers ----------------
__device__ __forceinline__ void ldm4(uint32_t* r, uint32_t addr) {
    asm volatile("ldmatrix.sync.aligned.m8n8.x4.shared.b16 {%0,%1,%2,%3}, [%4];\n"
                 : "=r"(r[0]), "=r"(r[1]), "=r"(r[2]), "=r"(r[3]) : "r"(addr));
}
__device__ __forceinline__ void mma16816(float* c, const uint32_t* a,
                                         uint32_t b0, uint32_t b1) {
    asm volatile(
        "mma.sync.aligned.m16n8k16.row.col.f32.f16.f16.f32 "
        "{%0,%1,%2,%3}, {%4,%5,%6,%7}, {%8,%9}, {%0,%1,%2,%3};\n"
        : "+f"(c[0]), "+f"(c[1]), "+f"(c[2]), "+f"(c[3])
        : "r"(a[0]), "r"(a[1]), "r"(a[2]), "r"(a[3]), "r"(b0), "r"(b1));
}
__device__ __forceinline__ void cp16(uint32_t dst, const void* src) {
    asm volatile("cp.async.cg.shared.global [%0], [%1], 16;" :: "r"(dst), "l"(src));
}
#define CP_COMMIT() asm volatile("cp.async.commit_group;" ::: "memory")
#define CP_WAIT0()  asm volatile("cp.async.wait_group 0;" ::: "memory")

// fp32 -> f16 hi + f16 lo residual, packed
__device__ __forceinline__ void cvt_split(float4 v, uint2& hi, uint2& lo) {
    __half2 h01 = __floats2half2_rn(v.x, v.y);
    __half2 h23 = __floats2half2_rn(v.z, v.w);
    float2 f01 = __half22float2(h01);
    float2 f23 = __half22float2(h23);
    __half2 l01 = __floats2half2_rn(v.x - f01.x, v.y - f01.y);
    __half2 l23 = __floats2half2_rn(v.z - f23.x, v.w - f23.y);
    hi.x = *(uint32_t*)&h01; hi.y = *(uint32_t*)&h23;
    lo.x = *(uint32_t*)&l01; lo.y = *(uint32_t*)&l23;
}

// ---------------------------------------------------------------------------
// Kernel 1: W -> W^T f16 hi/lo splits + zero g_best
// ---------------------------------------------------------------------------
__global__ void prep_kernel(const float* __restrict__ W) {
    int idx = blockIdx.x * blockDim.x + threadIdx.x;
    if (idx < N_PAD * D_DIM) {
        int n = idx / D_DIM;
        int k = idx - n * D_DIM;
        float w = (n < C_CLS) ? W[n * D_DIM + k] : 0.0f;
        __half h = __float2half_rn(w);
        g_BtH[idx] = h;
        g_BtL[idx] = __float2half_rn(w - __half2float(h));
    }
    if (idx < N_BAGS) g_best[idx] = 0ull;
}

// ---------------------------------------------------------------------------
// Kernel 2: split-f16 mma.sync GEMM, software-pipelined fragments
// ---------------------------------------------------------------------------
__global__ __launch_bounds__(NTHR, 2)
void main_kernel(const float* __restrict__ reps,
                 const int*   __restrict__ scope,
                 const int*   __restrict__ label,
                 const float* __restrict__ bias) {
    extern __shared__ __align__(16) __half sm[];
    __half* Ah = sm;                          // 2 stages each
    __half* Al = sm + 2 * A_STAGE;
    __half* Bh = sm + 4 * A_STAGE;
    __half* Bl = sm + 4 * A_STAGE + 2 * B_STAGE;
    float*  logits = (float*)sm;              // epilogue overlay
    __shared__ float s_inv[BM];

    const int tid  = threadIdx.x;
    const int lane = tid & 31;
    const int wrp  = tid >> 5;                // warp = rows wrp*16..+16
    const int mbase = wrp * 16;
    const int rowBase = blockIdx.x * BM;

    const uint32_t uAh = (uint32_t)__cvta_generic_to_shared(Ah);
    const uint32_t uAl = (uint32_t)__cvta_generic_to_shared(Al);
    const uint32_t uBh = (uint32_t)__cvta_generic_to_shared(Bh);
    const uint32_t uBl = (uint32_t)__cvta_generic_to_shared(Bl);

    float acc[NJ][4];
    #pragma unroll
    for (int j = 0; j < NJ; j++)
        #pragma unroll
        for (int q = 0; q < 4; q++) acc[j][q] = 0.0f;

    // ---- global A mapping ----
    const int ldRow = tid >> 4;               // 0..15
    const int ldCol = tid & 15;
    const float* aPtr = reps + (size_t)(rowBase + ldRow) * D_DIM + ldCol * 4;

    // ---- B cp.async mapping ----
    const int bRow = tid >> 2;                // 0..63
    const int bSeg = tid & 3;
    const __half* bhSrc = g_BtH + (size_t)bRow * D_DIM;
    const __half* blSrc = g_BtL + (size_t)bRow * D_DIM;
    const uint32_t bDstRow = (uint32_t)(bRow * B_STRIDE) * 2;

    // ---- ldmatrix offsets (halves) ----
    const int aOff = (mbase + (lane & 15)) * A_STRIDE + ((lane >> 4) << 3);
    const int bRowOff = (lane & 7) + ((lane >> 4) << 3);
    const int bColOff = ((lane >> 3) & 1) << 3;

    float4 ra[8];

    // ---- prologue: stage 0 ----
    #pragma unroll
    for (int i = 0; i < 2; i++) {
        int sg = bSeg + 4 * i;
        cp16(uBh + bDstRow + sg * 16, bhSrc + sg * 8);
        cp16(uBl + bDstRow + sg * 16, blSrc + sg * 8);
    }
    CP_COMMIT();
    #pragma unroll
    for (int i = 0; i < 8; i++)
        ra[i] = *(const float4*)(aPtr + (size_t)(16 * i) * D_DIM);
    #pragma unroll
    for (int i = 0; i < 8; i++) {
        uint2 hi, lo;
        cvt_split(ra[i], hi, lo);
        int off = (ldRow + 16 * i) * A_STRIDE + ldCol * 4;
        *(uint2*)(Ah + off) = hi;
        *(uint2*)(Al + off) = lo;
    }
    CP_WAIT0();
    __syncthreads();

    // ---- main loop ----
    for (int t = 0; t < NCHUNK; t++) {
        const int buf = t & 1;
        const bool more = (t + 1 < NCHUNK);

        if (more) {
            const int ko = (t + 1) * KC;
            const int nb = (t + 1) & 1;
            const uint32_t bsO = (uint32_t)(nb * B_STAGE) * 2;
            #pragma unroll
            for (int i = 0; i < 2; i++) {
                int sg = bSeg + 4 * i;
                cp16(uBh + bsO + bDstRow + sg * 16, bhSrc + ko + sg * 8);
                cp16(uBl + bsO + bDstRow + sg * 16, blSrc + ko + sg * 8);
            }
            CP_COMMIT();
            #pragma unroll
            for (int i = 0; i < 8; i++)
                ra[i] = *(const float4*)(aPtr + (size_t)(16 * i) * D_DIM + ko);
        }

        // ---- MMA section: software-pipelined fragment loads ----
        const uint32_t aStO = uint32_t(buf * A_STAGE) * 2;
        const uint32_t bStO = uint32_t(buf * B_STAGE) * 2;

        uint32_t afh[4], afl[4], nfh[4], nfl[4];
        uint32_t bh0[4], bl0[4], bh1[4], bl1[4];

        // preload A fragments for s=0
        ldm4(afh, uAh + aStO + (aOff + 0) * 2);
        ldm4(afl, uAl + aStO + (aOff + 0) * 2);

        #pragma unroll
        for (int s = 0; s < 4; s++) {
            // prefetch next s A fragments
            if (s < 3) {
                ldm4(nfh, uAh + aStO + (aOff + (s + 1) * 16) * 2);
                ldm4(nfl, uAl + aStO + (aOff + (s + 1) * 16) * 2);
            }
            // preload B pair p=0
            {
                int boff = (bRowOff) * B_STRIDE + s * 16 + bColOff;
                ldm4(bh0, uBh + bStO + boff * 2);
                ldm4(bl0, uBl + bStO + boff * 2);
            }
            #pragma unroll
            for (int p = 0; p < 4; p++) {
                if (p < 3) {   // prefetch next B pair
                    int boff = (16 * (p + 1) + bRowOff) * B_STRIDE + s * 16 + bColOff;
                    ldm4(bh1, uBh + bStO + boff * 2);
                    ldm4(bl1, uBl + bStO + boff * 2);
                }
                const int j0 = 2 * p;
                // product-major interleave across the two j's of this pair
                mma16816(acc[j0], afh, bh0[0], bh0[1]);
                if (j0 + 1 < NJ) mma16816(acc[j0 + 1], afh, bh0[2], bh0[3]);
                mma16816(acc[j0], afh, bl0[0], bl0[1]);
                if (j0 + 1 < NJ) mma16816(acc[j0 + 1], afh, bl0[2], bl0[3]);
                mma16816(acc[j0], afl, bh0[0], bh0[1]);
                if (j0 + 1 < NJ) mma16816(acc[j0 + 1], afl, bh0[2], bh0[3]);
                if (p < 3) {   // rotate
                    #pragma unroll
                    for (int q = 0; q < 4; q++) { bh0[q] = bh1[q]; bl0[q] = bl1[q]; }
                }
            }
            if (s < 3) {
                #pragma unroll
                for (int q = 0; q < 4; q++) { afh[q] = nfh[q]; afl[q] = nfl[q]; }
            }
        }

        if (more) {
            const int nb = (t + 1) & 1;
            #pragma unroll
            for (int i = 0; i < 8; i++) {
                uint2 hi, lo;
                cvt_split(ra[i], hi, lo);
                int off = nb * A_STAGE + (ldRow + 16 * i) * A_STRIDE + ldCol * 4;
                *(uint2*)(Ah + off) = hi;
                *(uint2*)(Al + off) = lo;
            }
            CP_WAIT0();
        }
        __syncthreads();
    }

    // ---- epilogue: acc + bias -> logits smem ----
    {
        const int r0 = mbase + (lane >> 2);
        const int cb = (lane & 3) * 2;
        #pragma unroll
        for (int j = 0; j < NJ; j++) {
            int c = j * 8 + cb;
            float b0 = (c     < C_CLS) ? bias[c]     : 0.0f;
            float b1 = (c + 1 < C_CLS) ? bias[c + 1] : 0.0f;
            logits[r0 * L_STRIDE + c]           = acc[j][0] + b0;
            logits[r0 * L_STRIDE + c + 1]       = acc[j][1] + b1;
            logits[(r0 + 8) * L_STRIDE + c]     = acc[j][2] + b0;
            logits[(r0 + 8) * L_STRIDE + c + 1] = acc[j][3] + b1;
        }
    }
    __syncthreads();

    // ---- per-row softmax + bag argmax ----
    if (tid < BM) {
        const int r = tid;
        float* lrow = logits + r * L_STRIDE;
        float mx = -1e30f;
        #pragma unroll
        for (int c = 0; c < C_CLS; c++) mx = fmaxf(mx, lrow[c]);
        float s = 0.0f;
        #pragma unroll
        for (int c = 0; c < C_CLS; c++) {
            float e = expf(lrow[c] - mx);
            lrow[c] = e;
            s += e;
        }
        float is = 1.0f / s;
        s_inv[r] = is;

        const int row = rowBase + r;
        int lo = 0, hi = N_BAGS;
        while (hi - lo > 1) {
            int mid = (lo + hi) >> 1;
            if (scope[mid] <= row) lo = mid; else hi = mid;
        }
        const int lbl = label[lo];
        const float lp = lrow[lbl] * is;
        ull pk = ((ull)__float_as_uint(lp) << 32) | (unsigned)(~row);
        atomicMax(&g_best[lo], pk);
    }
    __syncthreads();

    // ---- coalesced prob write ----
    for (int idx = tid; idx < BM * C_CLS; idx += NTHR) {
        int rr = idx / C_CLS;
        int cc = idx - rr * C_CLS;
        g_probs[(size_t)rowBase * C_CLS + idx] = logits[rr * L_STRIDE + cc] * s_inv[rr];
    }
}

// ---------------------------------------------------------------------------
// Kernel 3: gather selected rows
// ---------------------------------------------------------------------------
__global__ void gather_kernel(float* __restrict__ out) {
    int idx = blockIdx.x * blockDim.x + threadIdx.x;
    if (idx < N_BAGS * C_CLS) {
        int b = idx / C_CLS;
        int c = idx - b * C_CLS;
        unsigned sel = ~(unsigned)g_best[b];
        out[idx] = g_probs[(size_t)sel * C_CLS + c];
    }
}

// ---------------------------------------------------------------------------
extern "C" void kernel_launch(void* const* d_in, const int* in_sizes, int n_in,
                              void* d_out, int out_size) {
    const float* reps  = (const float*)d_in[0];
    const int*   scope = (const int*)  d_in[1];
    const int*   label = (const int*)  d_in[2];
    const float* W     = (const float*)d_in[3];
    const float* b     = (const float*)d_in[4];
    float* out = (float*)d_out;

    cudaFuncSetAttribute(main_kernel,
                         cudaFuncAttributeMaxDynamicSharedMemorySize, SMEM_BYTES);

    prep_kernel<<<(N_PAD * D_DIM + 255) / 256, 256>>>(W);
    main_kernel<<<N_SENT / BM, NTHR, SMEM_BYTES>>>(reps, scope, label, b);
    gather_kernel<<<(N_BAGS * C_CLS + 255) / 256, 256>>>(out);
}

// round 7
// speedup vs baseline: 1.0918x; 1.0918x over previous
#include <cuda_runtime.h>
#include <cuda_fp16.h>
#include <cstdint>

// Problem constants
#define N_SENT 65536
#define D_DIM  2304
#define N_BAGS 4096
#define C_CLS  53
#define N_PAD  64
#define NJ     7            // n8 blocks computed (cols 0..55)
#define BM     256          // rows per CTA
#define KC     64
#define NCHUNK (D_DIM / KC) // 36
#define NTHR   256

typedef unsigned long long ull;

// ---------------- global scratch ----------------
__device__ __half g_BtH[N_PAD * D_DIM];   // W^T [n][k] f16 hi (zero-padded rows)
__device__ __half g_BtL[N_PAD * D_DIM];   // f16 lo residual
__device__ float  g_probs[(size_t)N_SENT * C_CLS];
__device__ ull    g_best[N_BAGS];

// ---------------- smem geometry (halves) ----------------
#define A_STRIDE 72
#define B_STRIDE 72
#define A_STAGE  (BM * A_STRIDE)      // 18432 halves
#define B_STAGE  (N_PAD * B_STRIDE)   // 4608
#define SMEM_BYTES ((4 * A_STAGE + 4 * B_STAGE) * 2)   // 184320 bytes
#define L_STRIDE 65

// ---------------- PTX helpers ----------------
__device__ __forceinline__ void ldm4(uint32_t* r, uint32_t addr) {
    asm volatile("ldmatrix.sync.aligned.m8n8.x4.shared.b16 {%0,%1,%2,%3}, [%4];\n"
                 : "=r"(r[0]), "=r"(r[1]), "=r"(r[2]), "=r"(r[3]) : "r"(addr));
}
__device__ __forceinline__ void mma16816(float* c, const uint32_t* a,
                                         uint32_t b0, uint32_t b1) {
    asm volatile(
        "mma.sync.aligned.m16n8k16.row.col.f32.f16.f16.f32 "
        "{%0,%1,%2,%3}, {%4,%5,%6,%7}, {%8,%9}, {%0,%1,%2,%3};\n"
        : "+f"(c[0]), "+f"(c[1]), "+f"(c[2]), "+f"(c[3])
        : "r"(a[0]), "r"(a[1]), "r"(a[2]), "r"(a[3]), "r"(b0), "r"(b1));
}
__device__ __forceinline__ void cp16(uint32_t dst, const void* src) {
    asm volatile("cp.async.cg.shared.global [%0], [%1], 16;" :: "r"(dst), "l"(src));
}
#define CP_COMMIT() asm volatile("cp.async.commit_group;" ::: "memory")
#define CP_WAIT0()  asm volatile("cp.async.wait_group 0;" ::: "memory")

// fp32 -> f16 hi + f16 lo residual, packed
__device__ __forceinline__ void cvt_split(float4 v, uint2& hi, uint2& lo) {
    __half2 h01 = __floats2half2_rn(v.x, v.y);
    __half2 h23 = __floats2half2_rn(v.z, v.w);
    float2 f01 = __half22float2(h01);
    float2 f23 = __half22float2(h23);
    __half2 l01 = __floats2half2_rn(v.x - f01.x, v.y - f01.y);
    __half2 l23 = __floats2half2_rn(v.z - f23.x, v.w - f23.y);
    hi.x = *(uint32_t*)&h01; hi.y = *(uint32_t*)&h23;
    lo.x = *(uint32_t*)&l01; lo.y = *(uint32_t*)&l23;
}

// ---------------------------------------------------------------------------
// Kernel 1: W -> W^T f16 hi/lo splits + zero g_best
// ---------------------------------------------------------------------------
__global__ void prep_kernel(const float* __restrict__ W) {
    int idx = blockIdx.x * blockDim.x + threadIdx.x;
    if (idx < N_PAD * D_DIM) {
        int n = idx / D_DIM;
        int k = idx - n * D_DIM;
        float w = (n < C_CLS) ? W[n * D_DIM + k] : 0.0f;
        __half h = __float2half_rn(w);
        g_BtH[idx] = h;
        g_BtL[idx] = __float2half_rn(w - __half2float(h));
    }
    if (idx < N_BAGS) g_best[idx] = 0ull;
}

// ---------------------------------------------------------------------------
// Kernel 2: split-f16 mma.sync GEMM, 32 rows/warp (B fragments amortized 2x)
// ---------------------------------------------------------------------------
__global__ __launch_bounds__(NTHR, 1)
void main_kernel(const float* __restrict__ reps,
                 const int*   __restrict__ scope,
                 const int*   __restrict__ label,
                 const float* __restrict__ bias) {
    extern __shared__ __align__(16) __half sm[];
    __half* Ah = sm;                          // 2 stages
    __half* Al = sm + 2 * A_STAGE;
    __half* Bh = sm + 4 * A_STAGE;
    __half* Bl = sm + 4 * A_STAGE + 2 * B_STAGE;
    float*  logits = (float*)sm;              // epilogue overlay (256 x 65 floats)
    __shared__ float s_inv[BM];

    const int tid  = threadIdx.x;
    const int lane = tid & 31;
    const int wrp  = tid >> 5;                // warp = rows wrp*32 .. +32
    const int rowBase = blockIdx.x * BM;

    const uint32_t uAh = (uint32_t)__cvta_generic_to_shared(Ah);
    const uint32_t uAl = (uint32_t)__cvta_generic_to_shared(Al);
    const uint32_t uBh = (uint32_t)__cvta_generic_to_shared(Bh);
    const uint32_t uBl = (uint32_t)__cvta_generic_to_shared(Bl);

    float acc[2][NJ][4];
    #pragma unroll
    for (int i = 0; i < 2; i++)
        #pragma unroll
        for (int j = 0; j < NJ; j++)
            #pragma unroll
            for (int q = 0; q < 4; q++) acc[i][j][q] = 0.0f;

    // ---- global A mapping: 16 float4 per thread per stage (rows ldRow+16i) ----
    const int ldRow = tid >> 4;               // 0..15
    const int ldCol = tid & 15;
    const float* aPtr = reps + (size_t)(rowBase + ldRow) * D_DIM + ldCol * 4;

    // ---- B cp.async mapping ----
    const int bRow = tid >> 2;                // 0..63
    const int bSeg = tid & 3;
    const __half* bhSrc = g_BtH + (size_t)bRow * D_DIM;
    const __half* blSrc = g_BtL + (size_t)bRow * D_DIM;
    const uint32_t bDstRow = (uint32_t)(bRow * B_STRIDE) * 2;

    // ---- ldmatrix offsets (halves) ----
    int aOff[2];
    #pragma unroll
    for (int i = 0; i < 2; i++)
        aOff[i] = (wrp * 32 + i * 16 + (lane & 15)) * A_STRIDE + ((lane >> 4) << 3);
    const int bRowOff = (lane & 7) + ((lane >> 4) << 3);
    const int bColOff = ((lane >> 3) & 1) << 3;

    float4 ra[16];

    // ---- prologue: stage 0 ----
    #pragma unroll
    for (int i = 0; i < 2; i++) {
        int sg = bSeg + 4 * i;
        cp16(uBh + bDstRow + sg * 16, bhSrc + sg * 8);
        cp16(uBl + bDstRow + sg * 16, blSrc + sg * 8);
    }
    CP_COMMIT();
    #pragma unroll
    for (int i = 0; i < 16; i++)
        ra[i] = *(const float4*)(aPtr + (size_t)(16 * i) * D_DIM);
    #pragma unroll
    for (int i = 0; i < 16; i++) {
        uint2 hi, lo;
        cvt_split(ra[i], hi, lo);
        int off = (ldRow + 16 * i) * A_STRIDE + ldCol * 4;
        *(uint2*)(Ah + off) = hi;
        *(uint2*)(Al + off) = lo;
    }
    CP_WAIT0();
    __syncthreads();

    // ---- main loop ----
    for (int t = 0; t < NCHUNK; t++) {
        const int buf = t & 1;
        const bool more = (t + 1 < NCHUNK);

        if (more) {
            const int ko = (t + 1) * KC;
            const int nb = (t + 1) & 1;
            const uint32_t bsO = (uint32_t)(nb * B_STAGE) * 2;
            #pragma unroll
            for (int i = 0; i < 2; i++) {
                int sg = bSeg + 4 * i;
                cp16(uBh + bsO + bDstRow + sg * 16, bhSrc + ko + sg * 8);
                cp16(uBl + bsO + bDstRow + sg * 16, blSrc + ko + sg * 8);
            }
            CP_COMMIT();
            #pragma unroll
            for (int i = 0; i < 16; i++)
                ra[i] = *(const float4*)(aPtr + (size_t)(16 * i) * D_DIM + ko);
        }

        // ---- MMA section ----
        const uint32_t aStO = uint32_t(buf * A_STAGE) * 2;
        const uint32_t bStO = uint32_t(buf * B_STAGE) * 2;
        #pragma unroll
        for (int s = 0; s < 4; s++) {
            uint32_t afh[2][4], afl[2][4];
            #pragma unroll
            for (int i = 0; i < 2; i++) {
                ldm4(afh[i], uAh + aStO + (aOff[i] + s * 16) * 2);
                ldm4(afl[i], uAl + aStO + (aOff[i] + s * 16) * 2);
            }
            uint32_t bfh[16], bfl[16];
            #pragma unroll
            for (int p = 0; p < 4; p++) {
                int boff = (16 * p + bRowOff) * B_STRIDE + s * 16 + bColOff;
                ldm4(&bfh[4 * p], uBh + bStO + boff * 2);
                ldm4(&bfl[4 * p], uBl + bStO + boff * 2);
            }
            // 3 products, B fragments reused across both m-fragments
            #pragma unroll
            for (int j = 0; j < NJ; j++) {
                mma16816(acc[0][j], afh[0], bfh[2 * j], bfh[2 * j + 1]);
                mma16816(acc[1][j], afh[1], bfh[2 * j], bfh[2 * j + 1]);
            }
            #pragma unroll
            for (int j = 0; j < NJ; j++) {
                mma16816(acc[0][j], afh[0], bfl[2 * j], bfl[2 * j + 1]);
                mma16816(acc[1][j], afh[1], bfl[2 * j], bfl[2 * j + 1]);
            }
            #pragma unroll
            for (int j = 0; j < NJ; j++) {
                mma16816(acc[0][j], afl[0], bfh[2 * j], bfh[2 * j + 1]);
                mma16816(acc[1][j], afl[1], bfh[2 * j], bfh[2 * j + 1]);
            }
        }

        if (more) {
            const int nb = (t + 1) & 1;
            #pragma unroll
            for (int i = 0; i < 16; i++) {
                uint2 hi, lo;
                cvt_split(ra[i], hi, lo);
                int off = nb * A_STAGE + (ldRow + 16 * i) * A_STRIDE + ldCol * 4;
                *(uint2*)(Ah + off) = hi;
                *(uint2*)(Al + off) = lo;
            }
            CP_WAIT0();
        }
        __syncthreads();
    }

    // ---- epilogue: acc + bias -> logits smem ----
    {
        const int cb = (lane & 3) * 2;
        #pragma unroll
        for (int i = 0; i < 2; i++) {
            const int r0 = wrp * 32 + i * 16 + (lane >> 2);
            #pragma unroll
            for (int j = 0; j < NJ; j++) {
                int c = j * 8 + cb;
                float b0 = (c     < C_CLS) ? bias[c]     : 0.0f;
                float b1 = (c + 1 < C_CLS) ? bias[c + 1] : 0.0f;
                logits[r0 * L_STRIDE + c]           = acc[i][j][0] + b0;
                logits[r0 * L_STRIDE + c + 1]       = acc[i][j][1] + b1;
                logits[(r0 + 8) * L_STRIDE + c]     = acc[i][j][2] + b0;
                logits[(r0 + 8) * L_STRIDE + c + 1] = acc[i][j][3] + b1;
            }
        }
    }
    __syncthreads();

    // ---- per-row softmax + bag argmax (256 threads <-> 256 rows) ----
    {
        const int r = tid;
        float* lrow = logits + r * L_STRIDE;
        float mx = -1e30f;
        #pragma unroll
        for (int c = 0; c < C_CLS; c++) mx = fmaxf(mx, lrow[c]);
        float s = 0.0f;
        #pragma unroll
        for (int c = 0; c < C_CLS; c++) {
            float e = expf(lrow[c] - mx);
            lrow[c] = e;
            s += e;
        }
        float is = 1.0f / s;
        s_inv[r] = is;

        const int row = rowBase + r;
        int lo = 0, hi = N_BAGS;
        while (hi - lo > 1) {
            int mid = (lo + hi) >> 1;
            if (scope[mid] <= row) lo = mid; else hi = mid;
        }
        const int lbl = label[lo];
        const float lp = lrow[lbl] * is;
        ull pk = ((ull)__float_as_uint(lp) << 32) | (unsigned)(~row);
        atomicMax(&g_best[lo], pk);
    }
    __syncthreads();

    // ---- coalesced prob write ----
    for (int idx = tid; idx < BM * C_CLS; idx += NTHR) {
        int rr = idx / C_CLS;
        int cc = idx - rr * C_CLS;
        g_probs[(size_t)rowBase * C_CLS + idx] = logits[rr * L_STRIDE + cc] * s_inv[rr];
    }
}

// ---------------------------------------------------------------------------
// Kernel 3: gather selected rows
// ---------------------------------------------------------------------------
__global__ void gather_kernel(float* __restrict__ out) {
    int idx = blockIdx.x * blockDim.x + threadIdx.x;
    if (idx < N_BAGS * C_CLS) {
        int b = idx / C_CLS;
        int c = idx - b * C_CLS;
        unsigned sel = ~(unsigned)g_best[b];
        out[idx] = g_probs[(size_t)sel * C_CLS + c];
    }
}

// ---------------------------------------------------------------------------
extern "C" void kernel_launch(void* const* d_in, const int* in_sizes, int n_in,
                              void* d_out, int out_size) {
    const float* reps  = (const float*)d_in[0];
    const int*   scope = (const int*)  d_in[1];
    const int*   label = (const int*)  d_in[2];
    const float* W     = (const float*)d_in[3];
    const float* b     = (const float*)d_in[4];
    float* out = (float*)d_out;

    cudaFuncSetAttribute(main_kernel,
                         cudaFuncAttributeMaxDynamicSharedMemorySize, SMEM_BYTES);

    prep_kernel<<<(N_PAD * D_DIM + 255) / 256, 256>>>(W);
    main_kernel<<<N_SENT / BM, NTHR, SMEM_BYTES>>>(reps, scope, label, b);
    gather_kernel<<<(N_BAGS * C_CLS + 255) / 256, 256>>>(out);
}